// round 15
// baseline (speedup 1.0000x reference)
#include <cuda_runtime.h>
#include <climits>

// Problem shape (fixed): B=4, C=1, D=64, H=256, W=256
#define SLICES      256                 // B*D
#define SPLIT       2                   // parts per slice
#define NBLOCKS     (SLICES * SPLIT)    // 512  -> single wave
#define THREADS     256
#define PART_F4     8192                // float4 per part (32768 elems)
#define ITERS       32                  // stages of 256 float4
#define STAGES      6                   // smem ring depth (48KB exactly, via union overlay)
#define PROLOG      5                   // stages issued up front
#define ROWS_PER_PART 128
#define TOTAL_ELEMS 16777216.0f
#define NBOX_ELEMS  1024.0f
#define LN2F        0.6931471805599453f

// Scratch (no allocation allowed) — partials per block
__device__ float        g_seg[NBLOCKS];
__device__ int4         g_box[NBLOCKS];   // x=minR, y=maxR, z=minC, w=maxC
__device__ unsigned int g_count = 0;

__device__ __forceinline__ void cpa16(void* sdst, const void* gsrc) {
    unsigned sa = (unsigned)__cvta_generic_to_shared(sdst);
    asm volatile("cp.async.cg.shared.global [%0], [%1], 16;" :: "r"(sa), "l"(gsrc) : "memory");
}
__device__ __forceinline__ void cpa_commit() {
    asm volatile("cp.async.commit_group;" ::: "memory");
}
__device__ __forceinline__ void cpa_wait4() {
    asm volatile("cp.async.wait_group 4;" ::: "memory");
}

__global__ void __launch_bounds__(THREADS) fused_kernel(
    const float4* __restrict__ x4p, const float4* __restrict__ t4p,
    const float*  __restrict__ tgt, float* __restrict__ out)
{
    // Ring and post-loop reduction arrays OVERLAY each other (union): the
    // reduction arrays are only touched after every warp has finished reading
    // the ring (enforced by the __syncthreads right after the main loop).
    __shared__ __align__(16) union SmemU {
        struct { float4 x[STAGES][THREADS]; float4 t[STAGES][THREADS]; } ring;  // 49152 B
        struct {
            float seg[8];
            int   mnR[8], mxR[8], mnC[8], mxC[8];
            float tseg[8], tbox[8];
            int   isLast;
        } post;
    } su;

    const int blk  = blockIdx.x;            // blk = slice*SPLIT + part
    const int tid  = threadIdx.x;
    const int part = blk & (SPLIT - 1);
    const int rowBase = part * ROWS_PER_PART;

    const float4* __restrict__ xb = x4p + (size_t)blk * PART_F4 + tid;
    const float4* __restrict__ tb = t4p + (size_t)blk * PART_F4 + tid;

    // Accumulators. Columns are FIXED per thread (stride 256 ≡ 0 mod 64).
    float cm0 = -1.0f, cm1 = -1.0f, cm2 = -1.0f, cm3 = -1.0f;
    float aL0 = 0.0f, aL1 = 0.0f;       // Σ (max(x,0) - x·t), two chains
    float accL2 = 0.0f;                 // Σ log2(Π(1+e^-|x|))
    unsigned rmask = 0;                 // bit k: any(x>0) in k-th visited row (32 rows)

    // ---- prologue: stages 0..4 in flight (5 groups; group s <-> stage s) ----
    #pragma unroll
    for (int s = 0; s < PROLOG; ++s) {
        cpa16(&su.ring.x[s][tid], xb + s * THREADS);
        cpa16(&su.ring.t[s][tid], tb + s * THREADS);
        cpa_commit();
    }

    // Each thread reads ONLY data it staged itself -> no __syncthreads in loop.
    // At iter k: committed groups 0..PROLOG+k-1; wait_group 4 completes 0..k
    // => stage k resident, 4 stages outstanding per warp (4KB in flight).
    int slot = 0;        // k mod STAGES
    int pfslot = PROLOG; // (k + PROLOG) mod STAGES
    #pragma unroll 4
    for (int k = 0; k < ITERS; ++k) {
        cpa_wait4();
        const float4 xv = su.ring.x[slot][tid];
        const float4 tv = su.ring.t[slot][tid];

        if (k + PROLOG < ITERS) {
            cpa16(&su.ring.x[pfslot][tid], xb + (k + PROLOG) * THREADS);
            cpa16(&su.ring.t[pfslot][tid], tb + (k + PROLOG) * THREADS);
        }
        cpa_commit();   // commit every iter (possibly empty) keeps group math uniform

        // one LG2 per 4 elements: log2((1+e0)(1+e1)(1+e2)(1+e3))
        float e0 = __expf(-fabsf(xv.x));
        float e1 = __expf(-fabsf(xv.y));
        float a01 = 1.0f + e0;
        float p01 = __fmaf_rn(e1, a01, a01);       // (1+e0)(1+e1)
        float e2 = __expf(-fabsf(xv.z));
        float e3 = __expf(-fabsf(xv.w));
        float a23 = 1.0f + e2;
        float p23 = __fmaf_rn(e3, a23, a23);       // (1+e2)(1+e3)
        accL2 += __log2f(p01 * p23);

        // linear terms: Σ max(x,0) - x·t, two chains
        aL0 += fmaxf(xv.x, 0.0f);
        aL0  = __fmaf_rn(-xv.x, tv.x, aL0);
        aL1 += fmaxf(xv.y, 0.0f);
        aL1  = __fmaf_rn(-xv.y, tv.y, aL1);
        aL0 += fmaxf(xv.z, 0.0f);
        aL0  = __fmaf_rn(-xv.z, tv.z, aL0);
        aL1 += fmaxf(xv.w, 0.0f);
        aL1  = __fmaf_rn(-xv.w, tv.w, aL1);

        // bbox: per-column running max + per-row any
        cm0 = fmaxf(cm0, xv.x);
        cm1 = fmaxf(cm1, xv.y);
        cm2 = fmaxf(cm2, xv.z);
        cm3 = fmaxf(cm3, xv.w);
        float m4 = fmaxf(fmaxf(xv.x, xv.y), fmaxf(xv.z, xv.w));
        if (m4 > 0.0f) rmask |= (1u << k);

        slot   = (slot   == STAGES - 1) ? 0 : slot + 1;
        pfslot = (pfslot == STAGES - 1) ? 0 : pfslot + 1;
    }

    // All warps done reading the ring before the overlaid post arrays are written.
    __syncthreads();

    // Decode per-thread bbox contribution
    int minR, maxR, minC, maxC;
    {
        const int rb = rowBase + (tid >> 6);   // rows visited: rb + 4k, k=0..31
        if (rmask) {
            minR = rb + 4 * (__ffs(rmask) - 1);
            maxR = rb + 4 * (31 - __clz(rmask));
        } else { minR = INT_MAX; maxR = -1; }

        const int cb = (tid & 63) << 2;
        unsigned cmsk = (cm0 > 0.0f ? 1u : 0u) | (cm1 > 0.0f ? 2u : 0u)
                      | (cm2 > 0.0f ? 4u : 0u) | (cm3 > 0.0f ? 8u : 0u);
        if (cmsk) {
            minC = cb + (__ffs(cmsk) - 1);
            maxC = cb + (31 - __clz(cmsk));
        } else { minC = INT_MAX; maxC = -1; }
    }

    float seg = (aL0 + aL1) + LN2F * accL2;

    // ---- intra-warp reduction (shuffle) ----
    #pragma unroll
    for (int off = 16; off > 0; off >>= 1) {
        seg  += __shfl_xor_sync(0xFFFFFFFFu, seg,  off);
        minR  = min(minR, __shfl_xor_sync(0xFFFFFFFFu, minR, off));
        maxR  = max(maxR, __shfl_xor_sync(0xFFFFFFFFu, maxR, off));
        minC  = min(minC, __shfl_xor_sync(0xFFFFFFFFu, minC, off));
        maxC  = max(maxC, __shfl_xor_sync(0xFFFFFFFFu, maxC, off));
    }

    // ---- cross-warp reduction via overlaid smem (8 warps) ----
    const int wid = tid >> 5, lid = tid & 31;
    if (lid == 0) {
        su.post.seg[wid] = seg;
        su.post.mnR[wid] = minR; su.post.mxR[wid] = maxR;
        su.post.mnC[wid] = minC; su.post.mxC[wid] = maxC;
    }
    __syncthreads();
    if (tid == 0) {
        float rs = su.post.seg[0];
        int rmnR = su.post.mnR[0], rmxR = su.post.mxR[0];
        int rmnC = su.post.mnC[0], rmxC = su.post.mxC[0];
        #pragma unroll
        for (int w = 1; w < 8; ++w) {
            rs   += su.post.seg[w];
            rmnR  = min(rmnR, su.post.mnR[w]); rmxR = max(rmxR, su.post.mxR[w]);
            rmnC  = min(rmnC, su.post.mnC[w]); rmxC = max(rmxC, su.post.mxC[w]);
        }
        g_seg[blk] = rs;
        g_box[blk] = make_int4(rmnR, rmxR, rmnC, rmxC);
    }

    // ---- last-block-finishes tail ----
    __threadfence();
    if (tid == 0) {
        unsigned int c = atomicAdd(&g_count, 1u);
        su.post.isLast = (c == NBLOCKS - 1) ? 1 : 0;
    }
    __syncthreads();
    if (!su.post.isLast) return;

    // Tail: thread s handles slice s (256 threads)
    const int s = tid;
    float segT = 0.0f;
    int mnR = INT_MAX, mxR = -1, mnC = INT_MAX, mxC = -1;
    #pragma unroll
    for (int p = 0; p < SPLIT; ++p) {
        int idx = s * SPLIT + p;
        segT += __ldcg(&g_seg[idx]);
        int4 b = __ldcg(&g_box[idx]);
        mnR = min(mnR, b.x); mxR = max(mxR, b.y);
        mnC = min(mnC, b.z); mxC = max(mxC, b.w);
    }

    float bx, by, bw, bh;
    if (mxR < 0) {                       // empty mask
        bx = 0.0f; by = 0.0f; bw = 256.0f; bh = 256.0f;
    } else {
        bx = (float)mnC; by = (float)mnR;
        bw = (float)(mxC - mnC); bh = (float)(mxR - mnR);
    }

    float pred[4] = {bx, by, bw, bh};
    float l = 0.0f;
    #pragma unroll
    for (int j = 0; j < 4; ++j) {
        float d  = pred[j] - tgt[s * 4 + j];
        float ad = fabsf(d);
        l += (ad < 1.0f) ? 0.5f * d * d : ad - 0.5f;
    }

    // reduce 256 lanes: warp shuffle + smem
    #pragma unroll
    for (int off = 16; off > 0; off >>= 1) {
        segT += __shfl_xor_sync(0xFFFFFFFFu, segT, off);
        l    += __shfl_xor_sync(0xFFFFFFFFu, l,    off);
    }
    if (lid == 0) { su.post.tseg[wid] = segT; su.post.tbox[wid] = l; }
    __syncthreads();
    if (tid == 0) {
        float fs = 0.0f, fb = 0.0f;
        #pragma unroll
        for (int w = 0; w < 8; ++w) { fs += su.post.tseg[w]; fb += su.post.tbox[w]; }
        out[0] = fs / TOTAL_ELEMS;
        out[1] = fb / NBOX_ELEMS;
        g_count = 0;                     // reset for next graph replay
    }
}

extern "C" void kernel_launch(void* const* d_in, const int* in_sizes, int n_in,
                              void* d_out, int out_size)
{
    const float4* x4 = (const float4*)d_in[0];   // model_output
    const float4* t4 = (const float4*)d_in[1];   // target_masks
    const float*  tb = (const float*)d_in[2];    // target_bboxes
    float* out = (float*)d_out;

    fused_kernel<<<NBLOCKS, THREADS>>>(x4, t4, tb, out);
}